// round 3
// baseline (speedup 1.0000x reference)
#include <cuda_runtime.h>
#include <cuda_bf16.h>
#include <cstdint>

// Sobel conv (cross-correlation, SAME zero padding) + sign-difference maps.
// y[:,0]=Gx, y[:,1]=Gy ; y0[h,w]=sign(Gx[h,w])-sign(Gx[h,w+1]) ; y1[h,w]=sign(Gy[h,w])-sign(Gy[h+1,w])

#define IMG_H 1024
#define IMG_W 1024
#define TH 16           // output rows per block
#define TXV 32          // threads in x
#define OPT 4           // outputs per thread along W
#define TW (TXV * OPT)  // 128 output cols per block
#define NT (TXV * TH)   // 512 threads
#define SMH (TH + 3)    // 19 rows (h0-1 .. h0+17)
#define SMW 136         // cols w0-4 .. w0+131 (16B-aligned halo both sides)
#define SM_OFF 4        // smem col of global w0
#define NCH (SMW / 4)   // 34 float4 chunks per row

__device__ __forceinline__ float fsign(float v) {
    return (float)((v > 0.0f) - (v < 0.0f));
}

__global__ __launch_bounds__(NT)
void sobel_sign_kernel(const float* __restrict__ x,
                       float* __restrict__ y,
                       float* __restrict__ y0,
                       float* __restrict__ y1) {
    __shared__ __align__(16) float t[SMH][SMW];
    __shared__ __align__(16) float st0[TH][TW];   // staged y0 tile
    __shared__ __align__(16) float st1[TH][TW];   // staged y1 tile

    const int b  = blockIdx.z;
    const int h0 = blockIdx.y * TH;
    const int w0 = blockIdx.x * TW;

    const float* __restrict__ xb = x + (size_t)b * IMG_H * IMG_W;
    const int tid = threadIdx.y * TXV + threadIdx.x;

    // ---- vectorized halo-tile fill: 19 rows x 34 float4 chunks ----
    #pragma unroll
    for (int i = tid; i < SMH * NCH; i += NT) {
        const int rr = i / NCH;
        const int cc = i - rr * NCH;
        const int hh = h0 - 1 + rr;
        const int ww = w0 - 4 + cc * 4;
        float4 v = make_float4(0.f, 0.f, 0.f, 0.f);
        if ((unsigned)hh < (unsigned)IMG_H) {
            if (ww >= 0 && ww + 3 < IMG_W) {
                v = *reinterpret_cast<const float4*>(xb + (size_t)hh * IMG_W + ww);
            } else {
                float* ve = reinterpret_cast<float*>(&v);
                #pragma unroll
                for (int e = 0; e < 4; e++) {
                    const int we = ww + e;
                    if ((unsigned)we < (unsigned)IMG_W)
                        ve[e] = xb[(size_t)hh * IMG_W + we];
                }
            }
        }
        *reinterpret_cast<float4*>(&t[rr][cc * 4]) = v;
    }
    __syncthreads();

    const int tx = threadIdx.x;
    const int ty = threadIdx.y;
    const int c  = SM_OFF + tx * OPT;   // smem col of this thread's first output

    float gx0, gx1, gx2, gx3, gxr3;
    float gy0, gy1, gy2, gy3;
    float gd0, gd1, gd2, gd3;

#define ROW_LOAD(sr, s0, v0, v1)                                        \
    const float  s0 = t[sr][c - 1];                                     \
    const float4 v0 = *reinterpret_cast<const float4*>(&t[sr][c]);      \
    const float4 v1 = *reinterpret_cast<const float4*>(&t[sr][c + 4]);

    {   // row r-1 = ty : gx weight 1, gy top (+)
        ROW_LOAD(ty, s0, v0, v1)
        gx0 = s0   - v0.y;  gx1 = v0.x - v0.z;
        gx2 = v0.y - v0.w;  gx3 = v0.z - v1.x;
        gxr3 = v0.w - v1.y;
        gy0 = s0   + v0.y + 2.0f * v0.x;
        gy1 = v0.x + v0.z + 2.0f * v0.y;
        gy2 = v0.y + v0.w + 2.0f * v0.z;
        gy3 = v0.z + v1.x + 2.0f * v0.w;
    }
    {   // row r = ty+1 : gx weight 2, gy_d top (+)
        ROW_LOAD(ty + 1, s0, v0, v1)
        gx0 += 2.0f * (s0   - v0.y);  gx1 += 2.0f * (v0.x - v0.z);
        gx2 += 2.0f * (v0.y - v0.w);  gx3 += 2.0f * (v0.z - v1.x);
        gxr3 += 2.0f * (v0.w - v1.y);
        gd0 = s0   + v0.y + 2.0f * v0.x;
        gd1 = v0.x + v0.z + 2.0f * v0.y;
        gd2 = v0.y + v0.w + 2.0f * v0.z;
        gd3 = v0.z + v1.x + 2.0f * v0.w;
    }
    {   // row r+1 = ty+2 : gx weight 1, gy bottom (-)
        ROW_LOAD(ty + 2, s0, v0, v1)
        gx0 += s0   - v0.y;  gx1 += v0.x - v0.z;
        gx2 += v0.y - v0.w;  gx3 += v0.z - v1.x;
        gxr3 += v0.w - v1.y;
        gy0 -= s0   + v0.y + 2.0f * v0.x;
        gy1 -= v0.x + v0.z + 2.0f * v0.y;
        gy2 -= v0.y + v0.w + 2.0f * v0.z;
        gy3 -= v0.z + v1.x + 2.0f * v0.w;
    }
    {   // row r+2 = ty+3 : gy_d bottom (-)
        ROW_LOAD(ty + 3, s0, v0, v1)
        gd0 -= s0   + v0.y + 2.0f * v0.x;
        gd1 -= v0.x + v0.z + 2.0f * v0.y;
        gd2 -= v0.y + v0.w + 2.0f * v0.z;
        gd3 -= v0.z + v1.x + 2.0f * v0.w;
    }
#undef ROW_LOAD

    const int h  = h0 + ty;
    const int wb = w0 + tx * OPT;

    // y stores: aligned float4, direct.
    float* __restrict__ yb = y + (size_t)b * 2 * IMG_H * IMG_W;
    *reinterpret_cast<float4*>(&yb[(size_t)h * IMG_W + wb]) =
        make_float4(gx0, gx1, gx2, gx3);
    *reinterpret_cast<float4*>(&yb[(size_t)IMG_H * IMG_W + (size_t)h * IMG_W + wb]) =
        make_float4(gy0, gy1, gy2, gy3);

    // Stage y0/y1 tiles in smem (one STS.128 per channel), then stream out coalesced.
    {
        const float sx0 = fsign(gx0), sx1 = fsign(gx1), sx2 = fsign(gx2), sx3 = fsign(gx3);
        *reinterpret_cast<float4*>(&st0[ty][tx * OPT]) =
            make_float4(sx0 - sx1, sx1 - sx2, sx2 - sx3, sx3 - fsign(gxr3));
        *reinterpret_cast<float4*>(&st1[ty][tx * OPT]) =
            make_float4(fsign(gy0) - fsign(gd0), fsign(gy1) - fsign(gd1),
                        fsign(gy2) - fsign(gd2), fsign(gy3) - fsign(gd3));
    }
    __syncthreads();

    // Coalesced writeback: 2048 elems/channel, 512 threads -> 4 each, stride NT.
    const size_t sd = (size_t)(IMG_H - 1) * (IMG_W - 1);
    const float* s0f = &st0[0][0];
    const float* s1f = &st1[0][0];
    #pragma unroll
    for (int j = 0; j < (TH * TW) / NT; j++) {
        const int e   = tid + j * NT;
        const int rr  = e >> 7;          // e / TW
        const int cc  = e & (TW - 1);    // e % TW
        const int gh  = h0 + rr;
        const int gw  = w0 + cc;
        if (gh < IMG_H - 1 && gw < IMG_W - 1) {
            const size_t o = (size_t)b * sd + (size_t)gh * (IMG_W - 1) + gw;
            y0[o] = s0f[e];
            y1[o] = s1f[e];
        }
    }
}

extern "C" void kernel_launch(void* const* d_in, const int* in_sizes, int n_in,
                              void* d_out, int out_size) {
    const float* x = (const float*)d_in[0];
    const int B = in_sizes[0] / (IMG_H * IMG_W);

    float* y  = (float*)d_out;
    float* y0 = y  + (size_t)B * 2 * IMG_H * IMG_W;
    float* y1 = y0 + (size_t)B * (IMG_H - 1) * (IMG_W - 1);

    dim3 block(TXV, TH, 1);
    dim3 grid(IMG_W / TW, IMG_H / TH, B);
    sobel_sign_kernel<<<grid, block>>>(x, y, y0, y1);
}

// round 4
// speedup vs baseline: 1.1503x; 1.1503x over previous
#include <cuda_runtime.h>
#include <cuda_bf16.h>
#include <cstdint>

// Sobel conv (cross-correlation, SAME zero padding) + sign-difference maps.
// Rolling-register design: no shared memory, no barriers.
// Each warp: 128-col strip (lane owns 4 consecutive cols), 16 output rows,
// loads 19 input rows with a 3-deep separable partial-sum window.
// Column halo via warp shuffles; row/col out-of-bounds -> zeros (SAME pad).

#define IMG_W 1024
#define IMG_H 1024
#define RS 16            // output rows per warp
#define NWARP 8          // warps per block
#define NT (NWARP * 32)

__device__ __forceinline__ float fsign(float v) {
    return (float)((v > 0.0f) - (v < 0.0f));
}

__global__ __launch_bounds__(NT, 4)
void sobel_sign_kernel(const float* __restrict__ x,
                       float* __restrict__ y,
                       float* __restrict__ y0,
                       float* __restrict__ y1) {
    const int lane = threadIdx.x & 31;
    const int wid  = threadIdx.x >> 5;
    const int b    = blockIdx.z;
    const int w0   = blockIdx.x * 128;                  // strip base col
    const int r0   = (blockIdx.y * NWARP + wid) * RS;   // first output row
    const int wb   = w0 + lane * 4;                     // lane base col

    const float* __restrict__ xb = x + (size_t)b * IMG_H * IMG_W;
    float* __restrict__ ybx = y + (size_t)b * 2 * IMG_H * IMG_W;
    float* __restrict__ yby = ybx + (size_t)IMG_H * IMG_W;
    const size_t sd    = (size_t)(IMG_H - 1) * (IMG_W - 1);
    const size_t obase = (size_t)b * sd;
    const bool lane0   = (lane == 0);
    const bool lane31  = (lane == 31);
    const bool has_l   = (w0 > 0);
    const bool has_r   = (w0 + 128 < IMG_W);
    const bool lastcol = (wb + 4 >= IMG_W);   // lane31 of last strip: col wb+3 == 1023

    // rolling state: horizontal diffs (5-wide, incl. col wb+4) and sums (4-wide)
    float hdP1[5] = {0,0,0,0,0}, hdP2[5] = {0,0,0,0,0};
    float hsP1[4] = {0,0,0,0},   hsP2[4] = {0,0,0,0};
    float sgyP[4] = {0,0,0,0};

    #pragma unroll
    for (int i = 0; i < RS + 3; i++) {
        const int j = r0 - 1 + i;                 // input row for this step
        const bool rowOK = (unsigned)j < (unsigned)IMG_H;

        float4 v = make_float4(0.f, 0.f, 0.f, 0.f);
        float lf = 0.f, rt1 = 0.f, rt2 = 0.f;
        if (rowOK) {
            v = *reinterpret_cast<const float4*>(xb + (size_t)j * IMG_W + wb);
            if (lane0 && has_l)
                lf = __ldg(xb + (size_t)j * IMG_W + (w0 - 1));
            if (lane31 && has_r) {
                const float2 t2 = *reinterpret_cast<const float2*>(
                    xb + (size_t)j * IMG_W + (w0 + 128));
                rt1 = t2.x; rt2 = t2.y;
            }
        }
        // column halo via shuffles
        float left = __shfl_up_sync(0xffffffffu, v.w, 1);
        float rr1  = __shfl_down_sync(0xffffffffu, v.x, 1);
        float rr2  = __shfl_down_sync(0xffffffffu, v.y, 1);
        if (lane0)  left = lf;
        if (lane31) { rr1 = rt1; rr2 = rt2; }

        // horizontal combos for row j
        float hd[5], hs[4];
        hd[0] = left - v.y;  hd[1] = v.x - v.z;  hd[2] = v.y - v.w;
        hd[3] = v.z - rr1;   hd[4] = v.w - rr2;
        hs[0] = fmaf(2.f, v.x, left + v.y);
        hs[1] = fmaf(2.f, v.y, v.x + v.z);
        hs[2] = fmaf(2.f, v.z, v.y + v.w);
        hs[3] = fmaf(2.f, v.w, v.z + rr1);

        if (i >= 2) {
            const int m = r0 + i - 2;             // gx/gy now complete for row m
            float gy[4], sgy[4];
            #pragma unroll
            for (int k = 0; k < 4; k++) {
                gy[k]  = hsP2[k] - hs[k];
                sgy[k] = fsign(gy[k]);
            }

            if (i <= RS + 1) {                    // emit y + y0 for rows r0..r0+15
                float gx[5], sx[5];
                #pragma unroll
                for (int k = 0; k < 5; k++)
                    gx[k] = fmaf(2.f, hdP1[k], hdP2[k] + hd[k]);
                #pragma unroll
                for (int k = 0; k < 5; k++) sx[k] = fsign(gx[k]);

                *reinterpret_cast<float4*>(ybx + (size_t)m * IMG_W + wb) =
                    make_float4(gx[0], gx[1], gx[2], gx[3]);
                *reinterpret_cast<float4*>(yby + (size_t)m * IMG_W + wb) =
                    make_float4(gy[0], gy[1], gy[2], gy[3]);

                if (m < IMG_H - 1) {
                    const size_t o = obase + (size_t)m * (IMG_W - 1) + wb;
                    y0[o + 0] = sx[0] - sx[1];
                    y0[o + 1] = sx[1] - sx[2];
                    y0[o + 2] = sx[2] - sx[3];
                    if (!lastcol) y0[o + 3] = sx[3] - sx[4];
                }
            }
            if (i >= 3) {
                const int m1 = m - 1;             // y1 row m1 needs gy[m1] and gy[m1+1]
                if (m1 < IMG_H - 1) {
                    const size_t o = obase + (size_t)m1 * (IMG_W - 1) + wb;
                    y1[o + 0] = sgyP[0] - sgy[0];
                    y1[o + 1] = sgyP[1] - sgy[1];
                    y1[o + 2] = sgyP[2] - sgy[2];
                    if (!lastcol) y1[o + 3] = sgyP[3] - sgy[3];
                }
            }
            #pragma unroll
            for (int k = 0; k < 4; k++) sgyP[k] = sgy[k];
        }
        // rotate window
        #pragma unroll
        for (int k = 0; k < 5; k++) { hdP2[k] = hdP1[k]; hdP1[k] = hd[k]; }
        #pragma unroll
        for (int k = 0; k < 4; k++) { hsP2[k] = hsP1[k]; hsP1[k] = hs[k]; }
    }
}

extern "C" void kernel_launch(void* const* d_in, const int* in_sizes, int n_in,
                              void* d_out, int out_size) {
    const float* x = (const float*)d_in[0];
    const int B = in_sizes[0] / (IMG_H * IMG_W);

    float* y  = (float*)d_out;
    float* y0 = y  + (size_t)B * 2 * IMG_H * IMG_W;
    float* y1 = y0 + (size_t)B * (IMG_H - 1) * (IMG_W - 1);

    dim3 block(NT, 1, 1);
    dim3 grid(IMG_W / 128, IMG_H / (RS * NWARP), B);
    sobel_sign_kernel<<<grid, block>>>(x, y, y0, y1);
}